// round 15
// baseline (speedup 1.0000x reference)
#include <cuda_runtime.h>
#include <cuda_bf16.h>
#include <cstdint>

#define BB 2
#define HH 32
#define SS 16384
#define DD 64
#define NHEADS (BB*HH)
#define SPLIT 32
#define CHUNK (SS/SPLIT)   /* 512 s-rows per phase1 item */
#define NIT (CHUNK/64)     /* 8 staging iterations */

#define TM 64
#define TILES_PER_HEAD (SS / TM)      /* 256 */
#define TIT 16
#define ITEMS2_PER_HEAD (TILES_PER_HEAD / TIT)   /* 16 */
#define NITEMS1 (NHEADS * SPLIT)                 /* 2048 */
#define NITEMS2 (NHEADS * ITEMS2_PER_HEAD)       /* 1024 */
#define GRID_P 296                               /* 2 CTAs x 148 SMs, all resident */

/* scratch (no runtime alloc) */
__device__ float g_part[(size_t)NHEADS * SPLIT * 4160];
__device__ float g_norm[(size_t)NHEADS * 64];
__device__ __nv_bfloat16 g_memT_hi[(size_t)NHEADS * 4096];
__device__ __nv_bfloat16 g_memT_lo[(size_t)NHEADS * 4096];
__device__ int g_done[NHEADS];
__device__ int g_red[NHEADS];

__device__ __forceinline__ float elu1(float x) {
    return x > 0.0f ? x + 1.0f : __expf(x);
}
__device__ __forceinline__ uint32_t smem_u32(const void* p) {
    uint32_t a;
    asm("{ .reg .u64 t; cvta.to.shared.u64 t, %1; cvt.u32.u64 %0, t; }" : "=r"(a) : "l"(p));
    return a;
}
__device__ __forceinline__ int ld_acq(const int* p) {
    int v; asm volatile("ld.acquire.gpu.global.s32 %0, [%1];" : "=r"(v) : "l"(p) : "memory");
    return v;
}
__device__ __forceinline__ void red_rel_add(int* p, int v) {
    asm volatile("red.release.gpu.global.add.s32 [%0], %1;" :: "l"(p), "r"(v) : "memory");
}
__device__ __forceinline__ void st_rel(int* p, int v) {
    asm volatile("st.release.gpu.global.s32 [%0], %1;" :: "l"(p), "r"(v) : "memory");
}
__device__ __forceinline__ void ldsm_x4(uint32_t& r0, uint32_t& r1, uint32_t& r2,
                                        uint32_t& r3, uint32_t addr) {
    asm volatile("ldmatrix.sync.aligned.m8n8.x4.shared.b16 {%0,%1,%2,%3}, [%4];"
                 : "=r"(r0), "=r"(r1), "=r"(r2), "=r"(r3) : "r"(addr));
}
__device__ __forceinline__ void ldsm_x4_t(uint32_t& r0, uint32_t& r1, uint32_t& r2,
                                          uint32_t& r3, uint32_t addr) {
    asm volatile("ldmatrix.sync.aligned.m8n8.x4.trans.shared.b16 {%0,%1,%2,%3}, [%4];"
                 : "=r"(r0), "=r"(r1), "=r"(r2), "=r"(r3) : "r"(addr));
}
__device__ __forceinline__ void mma_bf16(float* d, const uint32_t* a,
                                         uint32_t b0, uint32_t b1) {
    asm volatile(
        "mma.sync.aligned.m16n8k16.row.col.f32.bf16.bf16.f32 "
        "{%0,%1,%2,%3}, {%4,%5,%6,%7}, {%8,%9}, {%0,%1,%2,%3};"
        : "+f"(d[0]), "+f"(d[1]), "+f"(d[2]), "+f"(d[3])
        : "r"(a[0]), "r"(a[1]), "r"(a[2]), "r"(a[3]), "r"(b0), "r"(b1));
}

#define ASWZ(row, unit) (((uint32_t)(row) << 7) + ((((unit) ^ ((row) & 7)) & 7) << 4))

__device__ __forceinline__ uint32_t pack_bf16x2(float lo_val, float hi_val) {
    uint32_t r;
    asm("cvt.rn.bf16x2.f32 %0, %1, %2;" : "=r"(r) : "f"(hi_val), "f"(lo_val));
    return r;
}
__device__ __forceinline__ void split_store(char* hi, char* lo, float4 v,
                                            uint32_t off) {
    uint32_t h0 = pack_bf16x2(v.x, v.y);
    uint32_t h1 = pack_bf16x2(v.z, v.w);
    float hx = __uint_as_float(h0 << 16);
    float hy = __uint_as_float(h0 & 0xffff0000u);
    float hz = __uint_as_float(h1 << 16);
    float hw = __uint_as_float(h1 & 0xffff0000u);
    uint32_t l0 = pack_bf16x2(v.x - hx, v.y - hy);
    uint32_t l1 = pack_bf16x2(v.z - hz, v.w - hw);
    *(uint2*)(hi + off) = make_uint2(h0, h1);
    *(uint2*)(lo + off) = make_uint2(l0, l1);
}

/* dyn smem union layout: [0]=KH/AH [8192]=KL/AL [16384]=VH/BH [24576]=VL/BL
   [32768]=s_nrm(4KB)/sden(256B)  [36864]=role flag */
#define SM_NRM  32768
#define SM_FLAG 36864
#define SM_TOTAL 36992

__global__ void reset_flags() {
    int i = threadIdx.x;
    if (i < NHEADS) { g_done[i] = 0; g_red[i] = 0; }
}

__global__ void __launch_bounds__(256, 2)
infini_fused(const float* __restrict__ q, const float* __restrict__ kk,
             const float* __restrict__ vv, float* __restrict__ outg) {
    extern __shared__ __align__(128) char dyn[];

    const int bx   = blockIdx.x;
    const int tid  = threadIdx.x;
    const int wid  = tid >> 5;
    const int lane = tid & 31;
    const int mi   = wid >> 1;
    const int nh   = wid & 1;

    const uint32_t sb = smem_u32(dyn);
    int* role_p = (int*)(dyn + SM_FLAG);

    /* per-thread staging slots (shared by both phases) */
    int srow[4]; uint32_t soff[4];
    #pragma unroll
    for (int p = 0; p < 4; ++p) {
        int f = tid + p * 256;
        srow[p] = f >> 4;
        int c4 = (f & 15) * 4;
        soff[p] = ASWZ(srow[p], c4 >> 3) + ((c4 >> 2) & 1) * 8;
    }

    /* =================== PHASE 1 items =================== */
    for (int item = bx; item < NITEMS1; item += GRID_P) {
        const int head  = item / SPLIT;
        const int chunk = item % SPLIT;

        const float* kbase = kk + ((size_t)head * SS + (size_t)chunk * CHUNK) * DD
                                + (size_t)((tid & 15) * 4);
        const float* vbase = vv + ((size_t)head * SS + (size_t)chunk * CHUNK) * DD
                                + (size_t)((tid & 15) * 4);

        float acc[4][4] = {};
        float nrm[4]    = {};

        float4 pk[4], pv[4];
        #pragma unroll
        for (int p = 0; p < 4; ++p) {
            pk[p] = __ldcs((const float4*)(kbase + (size_t)srow[p] * DD));
            pv[p] = __ldcs((const float4*)(vbase + (size_t)srow[p] * DD));
        }

        for (int it = 0; it < NIT; ++it) {
            __syncthreads();
            #pragma unroll
            for (int p = 0; p < 4; ++p) {
                float4 kf = pk[p];
                kf.x = elu1(kf.x); kf.y = elu1(kf.y); kf.z = elu1(kf.z); kf.w = elu1(kf.w);
                nrm[0] += kf.x; nrm[1] += kf.y; nrm[2] += kf.z; nrm[3] += kf.w;
                split_store(dyn + 0,     dyn + 8192,  kf,    soff[p]);
                split_store(dyn + 16384, dyn + 24576, pv[p], soff[p]);
            }
            __syncthreads();

            if (it + 1 < NIT) {
                const float* kn = kbase + (size_t)(it + 1) * 64 * DD;
                const float* vn = vbase + (size_t)(it + 1) * 64 * DD;
                #pragma unroll
                for (int p = 0; p < 4; ++p) {
                    pk[p] = __ldcs((const float4*)(kn + (size_t)srow[p] * DD));
                    pv[p] = __ldcs((const float4*)(vn + (size_t)srow[p] * DD));
                }
            }

            #pragma unroll
            for (int ps = 0; ps < 3; ++ps) {
                const uint32_t ab = sb + ((ps == 2) ? 8192 : 0);
                const uint32_t bb = sb + 16384 + ((ps == 1) ? 8192 : 0);
                #pragma unroll
                for (int kt = 0; kt < 4; ++kt) {
                    uint32_t a[4];
                    {
                        int ar = kt * 16 + (lane & 7) + ((lane >> 4) << 3);
                        int au = mi * 2 + ((lane >> 3) & 1);
                        ldsm_x4_t(a[0], a[1], a[2], a[3], ab + ASWZ(ar, au));
                    }
                    uint32_t b[4][2];
                    #pragma unroll
                    for (int np = 0; np < 2; ++np) {
                        int br = kt * 16 + (lane & 7) + (((lane >> 3) & 1) << 3);
                        int bu = nh * 4 + np * 2 + (lane >> 4);
                        uint32_t r0, r1, r2, r3;
                        ldsm_x4_t(r0, r1, r2, r3, bb + ASWZ(br, bu));
                        b[np*2+0][0] = r0; b[np*2+0][1] = r1;
                        b[np*2+1][0] = r2; b[np*2+1][1] = r3;
                    }
                    #pragma unroll
                    for (int nt = 0; nt < 4; ++nt)
                        mma_bf16(acc[nt], a, b[nt][0], b[nt][1]);
                }
            }
        }

        /* write M partial */
        float* outp = g_part + (size_t)item * 4160;
        {
            int r_lo = mi * 16 + (lane >> 2);
            int r_hi = r_lo + 8;
            int c0   = nh * 32 + (lane & 3) * 2;
            #pragma unroll
            for (int nt = 0; nt < 4; ++nt) {
                *(float2*)&outp[r_lo * 64 + nt * 8 + c0] = make_float2(acc[nt][0], acc[nt][1]);
                *(float2*)&outp[r_hi * 64 + nt * 8 + c0] = make_float2(acc[nt][2], acc[nt][3]);
            }
        }
        /* norm: deterministic reduction */
        float* snrm = (float*)(dyn + SM_NRM);
        __syncthreads();   /* smem free (mma done) */
        snrm[tid*4+0] = nrm[0]; snrm[tid*4+1] = nrm[1];
        snrm[tid*4+2] = nrm[2]; snrm[tid*4+3] = nrm[3];
        __syncthreads();
        if (tid < 16) {
            float s0 = 0.f, s1 = 0.f, s2 = 0.f, s3 = 0.f;
            #pragma unroll
            for (int g = 0; g < 16; ++g) {
                s0 += snrm[(tid + 16*g)*4+0]; s1 += snrm[(tid + 16*g)*4+1];
                s2 += snrm[(tid + 16*g)*4+2]; s3 += snrm[(tid + 16*g)*4+3];
            }
            *(float4*)&outp[4096 + tid * 4] = make_float4(s0, s1, s2, s3);
        }
        __syncthreads();           /* all g_part stores program-order before release */
        __threadfence();
        if (tid == 0) red_rel_add(&g_done[head], 1);
    }

    /* =================== PHASE 2 items =================== */
    for (int item = bx; item < NITEMS2; item += GRID_P) {
        const int head = item / ITEMS2_PER_HEAD;
        const int t0   = (item % ITEMS2_PER_HEAD) * TIT;

        __syncthreads();   /* prior item's smem reads done */
        if (tid == 0) {
            while (ld_acq(&g_done[head]) < SPLIT) __nanosleep(200);
            *role_p = atomicCAS(&g_red[head], 0, 1);
        }
        __syncthreads();
        const int role = *role_p;
        if (role == 0) {
            /* this CTA reduces the head (deterministic fixed-order sum) */
            const size_t pbase = (size_t)head * SPLIT * 4160;
            for (int e = tid; e < 4160; e += 256) {
                float s = 0.f;
                #pragma unroll 8
                for (int c = 0; c < SPLIT; ++c)
                    s += g_part[pbase + (size_t)c * 4160 + e];
                if (e < 4096) {
                    int dk = e >> 6, dv = e & 63;
                    __nv_bfloat16 h = __float2bfloat16(s);
                    __nv_bfloat16 l = __float2bfloat16(s - __bfloat162float(h));
                    g_memT_hi[(size_t)head * 4096 + dv * 64 + dk] = h;
                    g_memT_lo[(size_t)head * 4096 + dv * 64 + dk] = l;
                } else {
                    g_norm[(size_t)head * 64 + (e - 4096)] = s;
                }
            }
            __syncthreads();
            __threadfence();
            if (tid == 0) st_rel(&g_red[head], 2);
        } else {
            if (tid == 0) {
                while (ld_acq(&g_red[head]) != 2) __nanosleep(200);
            }
            __syncthreads();
        }

        /* ---- B tiles (bf16 hi/lo, swizzled) ---- */
        {
            const __nv_bfloat16* bh = g_memT_hi + (size_t)head * 4096;
            const __nv_bfloat16* bl = g_memT_lo + (size_t)head * 4096;
            #pragma unroll
            for (int p = 0; p < 2; ++p) {
                int f = tid + p * 256;
                int r = f >> 3;
                int u = f & 7;
                uint32_t off = ASWZ(r, u);
                *(uint4*)(dyn + 16384 + off) = *(const uint4*)(bh + r * 64 + u * 8);
                *(uint4*)(dyn + 24576 + off) = *(const uint4*)(bl + r * 64 + u * 8);
            }
        }
        const float4 mynrm = *(const float4*)(g_norm + (size_t)head * 64 + (tid & 15) * 4);
        const float* qcol = q + ((size_t)head * SS) * DD + (size_t)((tid & 15) * 4);
        float* sden = (float*)(dyn + SM_NRM);

        float4 pq[4];
        {
            const int s0 = t0 * TM;
            #pragma unroll
            for (int p = 0; p < 4; ++p)
                pq[p] = __ldcs((const float4*)(qcol + (size_t)(s0 + srow[p]) * DD));
        }

        for (int it = 0; it < TIT; ++it) {
            const int s0 = (t0 + it) * TM;

            __syncthreads();

            #pragma unroll
            for (int p = 0; p < 4; ++p) {
                float4 v = pq[p];
                v.x = elu1(v.x); v.y = elu1(v.y); v.z = elu1(v.z); v.w = elu1(v.w);
                split_store(dyn + 0, dyn + 8192, v, soff[p]);
                float dp = v.x * mynrm.x + v.y * mynrm.y + v.z * mynrm.z + v.w * mynrm.w;
                dp += __shfl_xor_sync(0xffffffffu, dp, 1);
                dp += __shfl_xor_sync(0xffffffffu, dp, 2);
                dp += __shfl_xor_sync(0xffffffffu, dp, 4);
                dp += __shfl_xor_sync(0xffffffffu, dp, 8);
                if ((lane & 15) == 0) sden[srow[p]] = dp;
            }
            __syncthreads();

            if (it + 1 < TIT) {
                const int s1 = (t0 + it + 1) * TM;
                #pragma unroll
                for (int p = 0; p < 4; ++p)
                    pq[p] = __ldcs((const float4*)(qcol + (size_t)(s1 + srow[p]) * DD));
            }

            float acc[4][4];
            #pragma unroll
            for (int nt = 0; nt < 4; ++nt)
                #pragma unroll
                for (int e = 0; e < 4; ++e) acc[nt][e] = 0.f;

            #pragma unroll
            for (int ps = 0; ps < 3; ++ps) {
                const uint32_t abase = sb + ((ps == 2) ? 8192 : 0);
                const uint32_t bbase = sb + 16384 + ((ps == 1) ? 8192 : 0);
                #pragma unroll
                for (int kt = 0; kt < 4; ++kt) {
                    uint32_t a[4];
                    {
                        int ar = mi * 16 + (lane & 15);
                        ldsm_x4(a[0], a[1], a[2], a[3],
                                abase + ASWZ(ar, kt * 2 + (lane >> 4)));
                    }
                    uint32_t b[4][2];
                    #pragma unroll
                    for (int np = 0; np < 2; ++np) {
                        int br = nh * 32 + np * 16 + (lane & 7) + ((lane >> 4) << 3);
                        uint32_t r0, r1, r2, r3;
                        ldsm_x4(r0, r1, r2, r3,
                                bbase + ASWZ(br, kt * 2 + ((lane >> 3) & 1)));
                        b[np*2+0][0] = r0; b[np*2+0][1] = r1;
                        b[np*2+1][0] = r2; b[np*2+1][1] = r3;
                    }
                    #pragma unroll
                    for (int nt = 0; nt < 4; ++nt)
                        mma_bf16(acc[nt], a, b[nt][0], b[nt][1]);
                }
            }

            int r_lo = mi * 16 + (lane >> 2);
            int r_hi = r_lo + 8;
            float inv_lo = 1.0f / sden[r_lo];
            float inv_hi = 1.0f / sden[r_hi];
            float* obase = outg + ((size_t)head * SS + (size_t)s0) * DD;
            int c0 = nh * 32 + (lane & 3) * 2;
            #pragma unroll
            for (int nt = 0; nt < 4; ++nt) {
                __stcs((float2*)(obase + (size_t)r_lo * DD + nt * 8 + c0),
                       make_float2(acc[nt][0] * inv_lo, acc[nt][1] * inv_lo));
                __stcs((float2*)(obase + (size_t)r_hi * DD + nt * 8 + c0),
                       make_float2(acc[nt][2] * inv_hi, acc[nt][3] * inv_hi));
            }
        }
    }
}

extern "C" void kernel_launch(void* const* d_in, const int* in_sizes, int n_in,
                              void* d_out, int out_size) {
    const float* q = (const float*)d_in[0];
    const float* k = (const float*)d_in[1];
    const float* v = (const float*)d_in[2];
    float* out = (float*)d_out;

    reset_flags<<<1, 64>>>();
    infini_fused<<<GRID_P, 256, SM_TOTAL>>>(q, k, v, out);
}

// round 16
// speedup vs baseline: 1.3830x; 1.3830x over previous
#include <cuda_runtime.h>
#include <cuda_bf16.h>
#include <cstdint>

#define BB 2
#define HH 32
#define SS 16384
#define DD 64
#define NHEADS (BB*HH)
#define SPLIT 32
#define CHUNK (SS/SPLIT)   /* 512 s-rows per phase1 CTA */
#define NIT (CHUNK/64)     /* 8 staging iterations */

/* phase2 config: persistent over all tiles */
#define TM 64
#define TILES_PER_HEAD (SS / TM)      /* 256 */
#define NTILES (NHEADS * TILES_PER_HEAD)  /* 16384 */
#define GRID2 296                     /* one resident wave (2 CTAs x 148 SMs) */

/* scratch (no runtime alloc) */
__device__ float g_part[(size_t)NHEADS * SPLIT * 4160];
__device__ float g_norm[(size_t)NHEADS * 64];
__device__ __nv_bfloat16 g_memT_hi[(size_t)NHEADS * 4096];  /* [head][dv*64+dk] */
__device__ __nv_bfloat16 g_memT_lo[(size_t)NHEADS * 4096];

__device__ __forceinline__ float elu1(float x) {
    return x > 0.0f ? x + 1.0f : __expf(x);
}

__device__ __forceinline__ uint32_t smem_u32(const void* p) {
    uint32_t a;
    asm("{ .reg .u64 t; cvta.to.shared.u64 t, %1; cvt.u32.u64 %0, t; }" : "=r"(a) : "l"(p));
    return a;
}
__device__ __forceinline__ void ldsm_x4(uint32_t& r0, uint32_t& r1, uint32_t& r2,
                                        uint32_t& r3, uint32_t addr) {
    asm volatile("ldmatrix.sync.aligned.m8n8.x4.shared.b16 {%0,%1,%2,%3}, [%4];"
                 : "=r"(r0), "=r"(r1), "=r"(r2), "=r"(r3) : "r"(addr));
}
__device__ __forceinline__ void ldsm_x4_t(uint32_t& r0, uint32_t& r1, uint32_t& r2,
                                          uint32_t& r3, uint32_t addr) {
    asm volatile("ldmatrix.sync.aligned.m8n8.x4.trans.shared.b16 {%0,%1,%2,%3}, [%4];"
                 : "=r"(r0), "=r"(r1), "=r"(r2), "=r"(r3) : "r"(addr));
}
__device__ __forceinline__ void mma_bf16(float* d, const uint32_t* a,
                                         uint32_t b0, uint32_t b1) {
    asm volatile(
        "mma.sync.aligned.m16n8k16.row.col.f32.bf16.bf16.f32 "
        "{%0,%1,%2,%3}, {%4,%5,%6,%7}, {%8,%9}, {%0,%1,%2,%3};"
        : "+f"(d[0]), "+f"(d[1]), "+f"(d[2]), "+f"(d[3])
        : "r"(a[0]), "r"(a[1]), "r"(a[2]), "r"(a[3]), "r"(b0), "r"(b1));
}

/* swizzled byte offset: 128B rows, 16B units XOR'ed by row&7 */
#define ASWZ(row, unit) (((uint32_t)(row) << 7) + ((((unit) ^ ((row) & 7)) & 7) << 4))

__device__ __forceinline__ uint32_t pack_bf16x2(float lo_val, float hi_val) {
    uint32_t r;
    asm("cvt.rn.bf16x2.f32 %0, %1, %2;" : "=r"(r) : "f"(hi_val), "f"(lo_val));
    return r;
}
__device__ __forceinline__ void split_store(char* hi, char* lo, float4 v,
                                            uint32_t off) {
    uint32_t h0 = pack_bf16x2(v.x, v.y);
    uint32_t h1 = pack_bf16x2(v.z, v.w);
    float hx = __uint_as_float(h0 << 16);
    float hy = __uint_as_float(h0 & 0xffff0000u);
    float hz = __uint_as_float(h1 << 16);
    float hw = __uint_as_float(h1 & 0xffff0000u);
    uint32_t l0 = pack_bf16x2(v.x - hx, v.y - hy);
    uint32_t l1 = pack_bf16x2(v.z - hz, v.w - hw);
    *(uint2*)(hi + off) = make_uint2(h0, h1);
    *(uint2*)(lo + off) = make_uint2(l0, l1);
}

/* ============ Phase 1: M = kf^T @ v via mma.sync, pipelined staging ============ */
__global__ void __launch_bounds__(256, 2)
phase1_mma(const float* __restrict__ kk, const float* __restrict__ vv) {
    __shared__ __align__(128) char sKH[8192];
    __shared__ __align__(128) char sKL[8192];
    __shared__ __align__(128) char sVH[8192];
    __shared__ __align__(128) char sVL[8192];
    __shared__ float s_nrm[256][4];

    const int bx    = blockIdx.x;
    const int head  = bx / SPLIT;
    const int chunk = bx % SPLIT;
    const int tid   = threadIdx.x;
    const int wid   = tid >> 5;
    const int lane  = tid & 31;
    const int mi    = wid >> 1;
    const int nh    = wid & 1;

    const uint32_t aKH = smem_u32(sKH), aKL = smem_u32(sKL);
    const uint32_t aVH = smem_u32(sVH), aVL = smem_u32(sVL);

    int srow[4]; uint32_t soff[4];
    #pragma unroll
    for (int p = 0; p < 4; ++p) {
        int f = tid + p * 256;
        srow[p] = f >> 4;
        int c4 = (f & 15) * 4;
        soff[p] = ASWZ(srow[p], c4 >> 3) + ((c4 >> 2) & 1) * 8;
    }
    const float* kbase = kk + ((size_t)head * SS + (size_t)chunk * CHUNK) * DD
                            + (size_t)((tid & 15) * 4);
    const float* vbase = vv + ((size_t)head * SS + (size_t)chunk * CHUNK) * DD
                            + (size_t)((tid & 15) * 4);

    float acc[4][4] = {};
    float nrm[4]    = {};

    float4 pk[4], pv[4];
    #pragma unroll
    for (int p = 0; p < 4; ++p) {
        pk[p] = __ldcs((const float4*)(kbase + (size_t)srow[p] * DD));
        pv[p] = __ldcs((const float4*)(vbase + (size_t)srow[p] * DD));
    }

    for (int it = 0; it < NIT; ++it) {
        __syncthreads();
        #pragma unroll
        for (int p = 0; p < 4; ++p) {
            float4 kf = pk[p];
            kf.x = elu1(kf.x); kf.y = elu1(kf.y); kf.z = elu1(kf.z); kf.w = elu1(kf.w);
            nrm[0] += kf.x; nrm[1] += kf.y; nrm[2] += kf.z; nrm[3] += kf.w;
            split_store(sKH, sKL, kf, soff[p]);
            split_store(sVH, sVL, pv[p], soff[p]);
        }
        __syncthreads();

        if (it + 1 < NIT) {
            const float* kn = kbase + (size_t)(it + 1) * 64 * DD;
            const float* vn = vbase + (size_t)(it + 1) * 64 * DD;
            #pragma unroll
            for (int p = 0; p < 4; ++p) {
                pk[p] = __ldcs((const float4*)(kn + (size_t)srow[p] * DD));
                pv[p] = __ldcs((const float4*)(vn + (size_t)srow[p] * DD));
            }
        }

        #pragma unroll
        for (int ps = 0; ps < 3; ++ps) {
            const uint32_t ab = (ps == 2) ? aKL : aKH;
            const uint32_t bb = (ps == 1) ? aVL : aVH;
            #pragma unroll
            for (int kt = 0; kt < 4; ++kt) {
                uint32_t a[4];
                {
                    int ar = kt * 16 + (lane & 7) + ((lane >> 4) << 3);
                    int au = mi * 2 + ((lane >> 3) & 1);
                    ldsm_x4_t(a[0], a[1], a[2], a[3], ab + ASWZ(ar, au));
                }
                uint32_t b[4][2];
                #pragma unroll
                for (int np = 0; np < 2; ++np) {
                    int br = kt * 16 + (lane & 7) + (((lane >> 3) & 1) << 3);
                    int bu = nh * 4 + np * 2 + (lane >> 4);
                    uint32_t r0, r1, r2, r3;
                    ldsm_x4_t(r0, r1, r2, r3, bb + ASWZ(br, bu));
                    b[np*2+0][0] = r0; b[np*2+0][1] = r1;
                    b[np*2+1][0] = r2; b[np*2+1][1] = r3;
                }
                #pragma unroll
                for (int nt = 0; nt < 4; ++nt)
                    mma_bf16(acc[nt], a, b[nt][0], b[nt][1]);
            }
        }
    }

    float* outp = g_part + (size_t)bx * 4160;
    {
        int r_lo = mi * 16 + (lane >> 2);
        int r_hi = r_lo + 8;
        int c0   = nh * 32 + (lane & 3) * 2;
        #pragma unroll
        for (int nt = 0; nt < 4; ++nt) {
            *(float2*)&outp[r_lo * 64 + nt * 8 + c0] = make_float2(acc[nt][0], acc[nt][1]);
            *(float2*)&outp[r_hi * 64 + nt * 8 + c0] = make_float2(acc[nt][2], acc[nt][3]);
        }
    }
    s_nrm[tid][0] = nrm[0]; s_nrm[tid][1] = nrm[1];
    s_nrm[tid][2] = nrm[2]; s_nrm[tid][3] = nrm[3];
    __syncthreads();
    if (tid < 16) {
        float s0 = 0.f, s1 = 0.f, s2 = 0.f, s3 = 0.f;
        #pragma unroll
        for (int g = 0; g < 16; ++g) {
            s0 += s_nrm[tid + 16*g][0]; s1 += s_nrm[tid + 16*g][1];
            s2 += s_nrm[tid + 16*g][2]; s3 += s_nrm[tid + 16*g][3];
        }
        *(float4*)&outp[4096 + tid * 4] = make_float4(s0, s1, s2, s3);
    }
}

/* ------- Reduce: sum SPLIT partials; emit transposed bf16 hi/lo + fp32 norm ------- */
__global__ void __launch_bounds__(512) reduce_k() {
    const int head = blockIdx.x;
    for (int e = threadIdx.x; e < 4160; e += 512) {
        float s = 0.f;
        #pragma unroll 8
        for (int c = 0; c < SPLIT; ++c)
            s += __ldcs(&g_part[((size_t)head * SPLIT + c) * 4160 + e]);
        if (e < 4096) {
            int dk = e >> 6, dv = e & 63;
            __nv_bfloat16 h = __float2bfloat16(s);
            __nv_bfloat16 l = __float2bfloat16(s - __bfloat162float(h));
            g_memT_hi[(size_t)head * 4096 + dv * 64 + dk] = h;
            g_memT_lo[(size_t)head * 4096 + dv * 64 + dk] = l;
        } else {
            g_norm[(size_t)head * 64 + (e - 4096)] = s;
        }
    }
}

/* ====== Phase 2: persistent, balanced tile ranges, B reload on head change ====== */
__global__ void __launch_bounds__(256, 2)
phase2_mma(const float* __restrict__ q, float* __restrict__ outg) {
    __shared__ __align__(128) char sAH[8192];
    __shared__ __align__(128) char sAL[8192];
    __shared__ __align__(128) char sBH[8192];
    __shared__ __align__(128) char sBL[8192];
    __shared__ float sden[64];

    const int bx   = blockIdx.x;
    const int tid  = threadIdx.x;
    const int wid  = tid >> 5;
    const int lane = tid & 31;
    const int mi   = wid >> 1;
    const int nh   = wid & 1;

    const uint32_t aAH = smem_u32(sAH), aAL = smem_u32(sAL);
    const uint32_t aBH = smem_u32(sBH), aBL = smem_u32(sBL);

    /* balanced contiguous tile range: NTILES = GRID2*base + extra */
    const int base  = NTILES / GRID2;            /* 55 */
    const int extra = NTILES % GRID2;            /* 104 */
    const int t_begin = bx * base + (bx < extra ? bx : extra);
    const int t_end   = t_begin + base + (bx < extra ? 1 : 0);

    int srow[4]; uint32_t soff[4];
    #pragma unroll
    for (int p = 0; p < 4; ++p) {
        int f = tid + p * 256;
        srow[p] = f >> 4;
        int c4 = (f & 15) * 4;
        soff[p] = ASWZ(srow[p], c4 >> 3) + ((c4 >> 2) & 1) * 8;
    }
    const int mycol = (tid & 15) * 4;

    int cur_head = -1;
    float4 mynrm = make_float4(0.f, 0.f, 0.f, 0.f);

    /* prefetch first tile's Q */
    float4 pq[4];
    {
        const int t = t_begin;
        const int h = t / TILES_PER_HEAD;
        const float* qp = q + ((size_t)h * SS + (size_t)(t % TILES_PER_HEAD) * TM) * DD
                            + (size_t)mycol;
        #pragma unroll
        for (int p = 0; p < 4; ++p)
            pq[p] = __ldcs((const float4*)(qp + (size_t)srow[p] * DD));
    }

    for (int t = t_begin; t < t_end; ++t) {
        const int head = t / TILES_PER_HEAD;
        const int s0   = (t % TILES_PER_HEAD) * TM;

        __syncthreads();   /* prior tile done reading A/sden; B safe to swap */

        if (head != cur_head) {
            const __nv_bfloat16* bh = g_memT_hi + (size_t)head * 4096;
            const __nv_bfloat16* bl = g_memT_lo + (size_t)head * 4096;
            #pragma unroll
            for (int p = 0; p < 2; ++p) {
                int f = tid + p * 256;
                int r = f >> 3;
                int u = f & 7;
                uint32_t off = ASWZ(r, u);
                *(uint4*)(sBH + off) = *(const uint4*)(bh + r * 64 + u * 8);
                *(uint4*)(sBL + off) = *(const uint4*)(bl + r * 64 + u * 8);
            }
            mynrm = *(const float4*)(g_norm + (size_t)head * 64 + mycol);
            cur_head = head;
        }

        /* ---- stage A + fused denominator ---- */
        #pragma unroll
        for (int p = 0; p < 4; ++p) {
            float4 v = pq[p];
            v.x = elu1(v.x); v.y = elu1(v.y); v.z = elu1(v.z); v.w = elu1(v.w);
            split_store(sAH, sAL, v, soff[p]);
            float dp = v.x * mynrm.x + v.y * mynrm.y + v.z * mynrm.z + v.w * mynrm.w;
            dp += __shfl_xor_sync(0xffffffffu, dp, 1);
            dp += __shfl_xor_sync(0xffffffffu, dp, 2);
            dp += __shfl_xor_sync(0xffffffffu, dp, 4);
            dp += __shfl_xor_sync(0xffffffffu, dp, 8);
            if ((lane & 15) == 0) sden[srow[p]] = dp;
        }
        __syncthreads();

        /* prefetch next tile — LDGs overlap mma + epilogue */
        if (t + 1 < t_end) {
            const int tn = t + 1;
            const int hn = tn / TILES_PER_HEAD;
            const float* qp = q + ((size_t)hn * SS + (size_t)(tn % TILES_PER_HEAD) * TM) * DD
                                + (size_t)mycol;
            #pragma unroll
            for (int p = 0; p < 4; ++p)
                pq[p] = __ldcs((const float4*)(qp + (size_t)srow[p] * DD));
        }

        /* ---- 3-pass bf16 mma ---- */
        float acc[4][4];
        #pragma unroll
        for (int nt = 0; nt < 4; ++nt)
            #pragma unroll
            for (int e = 0; e < 4; ++e) acc[nt][e] = 0.f;

        #pragma unroll
        for (int ps = 0; ps < 3; ++ps) {
            const uint32_t abase = (ps == 2) ? aAL : aAH;
            const uint32_t bbase = (ps == 1) ? aBL : aBH;
            #pragma unroll
            for (int kt = 0; kt < 4; ++kt) {
                uint32_t a[4];
                {
                    int ar = mi * 16 + (lane & 15);
                    ldsm_x4(a[0], a[1], a[2], a[3],
                            abase + ASWZ(ar, kt * 2 + (lane >> 4)));
                }
                uint32_t b[4][2];
                #pragma unroll
                for (int np = 0; np < 2; ++np) {
                    int br = nh * 32 + np * 16 + (lane & 7) + ((lane >> 4) << 3);
                    uint32_t r0, r1, r2, r3;
                    ldsm_x4(r0, r1, r2, r3,
                            bbase + ASWZ(br, kt * 2 + ((lane >> 3) & 1)));
                    b[np*2+0][0] = r0; b[np*2+0][1] = r1;
                    b[np*2+1][0] = r2; b[np*2+1][1] = r3;
                }
                #pragma unroll
                for (int nt = 0; nt < 4; ++nt)
                    mma_bf16(acc[nt], a, b[nt][0], b[nt][1]);
            }
        }

        /* ---- epilogue ---- */
        int r_lo = mi * 16 + (lane >> 2);
        int r_hi = r_lo + 8;
        float inv_lo = 1.0f / sden[r_lo];
        float inv_hi = 1.0f / sden[r_hi];
        float* obase = outg + ((size_t)head * SS + (size_t)s0) * DD;
        int c0 = nh * 32 + (lane & 3) * 2;
        #pragma unroll
        for (int nt = 0; nt < 4; ++nt) {
            __stcs((float2*)(obase + (size_t)r_lo * DD + nt * 8 + c0),
                   make_float2(acc[nt][0] * inv_lo, acc[nt][1] * inv_lo));
            __stcs((float2*)(obase + (size_t)r_hi * DD + nt * 8 + c0),
                   make_float2(acc[nt][2] * inv_hi, acc[nt][3] * inv_hi));
        }
    }
}

extern "C" void kernel_launch(void* const* d_in, const int* in_sizes, int n_in,
                              void* d_out, int out_size) {
    const float* q = (const float*)d_in[0];
    const float* k = (const float*)d_in[1];
    const float* v = (const float*)d_in[2];
    float* out = (float*)d_out;

    phase1_mma<<<NHEADS * SPLIT, 256>>>(k, v);
    reduce_k<<<NHEADS, 512>>>();
    phase2_mma<<<GRID2, 256>>>(q, out);
}